// round 3
// baseline (speedup 1.0000x reference)
#include <cuda_runtime.h>
#include <math.h>
#include <float.h>
#include <stdint.h>

// Problem constants (fixed by setup_inputs)
#define Bc 16
#define Nc 21504           // 128^2 + 64^2 + 32^2 anchors
#define Mc 64
#define Cc 15
#define ABp 91             // angle bins + 1
#define BNc (Bc*Nc)        // 344064
#define NEGBLK (BNc/256)   // 1344
#define POSBLK 52          // 52*256 = 13312 >= max positives
#define CAND 768           // per-GT candidate cap (max in-box cells ~600)
#define EPSA 1e-9f
#define ANGLE_SCALE_F ((float)((3.14159265358979323846/2.0)/90.0))

// ---- device scratch (static; no allocations) ----
__device__ float4   g_dec[BNc*2];        // per anchor: {x,y,a,b},{c,det,lse,0} (candidates only)
__device__ int      g_fgm[BNc];          // (count<<20) | bm  (bm valid iff count==1)
__device__ int      g_m[BNc];
__device__ float    g_al[BNc];
__device__ float4   g_gt[Bc*Mc*3];       // per GT: {cx,cy,a,b},{c,det,hw,hh},{ca,sa,ang,0}
__device__ unsigned g_maxal[Bc*Mc], g_maxiou[Bc*Mc];
__device__ int      g_npos;
__device__ int      g_plist[16384];
__device__ double   g_negpart[NEGBLK];
__device__ double   g_ppart[POSBLK*5];

// ProbIoU Hellinger distance (eps=1e-3), fast transcendentals (err ~1e-6, budget 1e-3)
__device__ __forceinline__ float probiou_hd(float x1, float y1, float a1, float b1, float c1, float d1,
                                            float x2, float y2, float a2, float b2, float c2, float d2){
    float a = a1 + a2, b = b1 + b2, c = c1 + c2;
    float denom = a*b - c*c + 1e-3f;
    float dy = y1 - y2, dx = x1 - x2;
    float rd = __fdividef(1.0f, denom);
    float t1 = (a*dy*dy + b*dx*dx) * rd * 0.25f;
    float t2 = c * (-dx) * dy * rd * 0.5f;
    float t3 = 0.5f * __logf(denom * __fdividef(1.0f, 4.0f*sqrtf(d1*d2) + 1e-3f) + 1e-3f);
    float bd = fminf(fmaxf(t1 + t2 + t3, 1e-3f), 100.0f);
    return sqrtf(1.0f - __expf(-bd) + 1e-7f);
}

__device__ __forceinline__ float fast_sig(float x){
    return __fdividef(1.0f, 1.0f + __expf(-x));
}

// block reduction of a double; result valid on thread 0 (256-thread blocks)
__device__ __forceinline__ double block_red(double v){
    __shared__ double sred[8];
    #pragma unroll
    for (int o = 16; o; o >>= 1) v += __shfl_down_sync(0xffffffffu, v, o);
    int w = threadIdx.x >> 5, l = threadIdx.x & 31;
    if (l == 0) sred[w] = v;
    __syncthreads();
    if (w == 0){
        v = (l < 8) ? sred[l] : 0.0;
        #pragma unroll
        for (int o = 4; o; o >>= 1) v += __shfl_down_sync(0xffffffffu, v, o);
    }
    __syncthreads();
    return v;
}

// ---- K0: fused GT prep + g_fgm memset + pure-negative focal BCE ----
__global__ void k_prep(const float* __restrict__ cls, const float* __restrict__ gtb){
    int i = blockIdx.x*256 + threadIdx.x;
    g_fgm[i] = 0;
    if (i == 0) g_npos = 0;
    if (i < Bc*Mc){
        const float* g = gtb + i*5;
        float cx = g[0], cy = g[1], w = g[2], h = g[3], an = g[4];
        float ca = __cosf(an), sa = __sinf(an);
        float A = w*w/12.0f, B = h*h/12.0f;
        float ga = A*ca*ca + B*sa*sa;
        float gb = A*sa*sa + B*ca*ca;
        float gc = (A - B)*ca*sa;
        float gd = fmaxf(ga*gb - gc*gc, 0.0f);
        g_gt[i*3+0] = make_float4(cx, cy, ga, gb);
        g_gt[i*3+1] = make_float4(gc, gd, w*0.5f, h*0.5f);
        g_gt[i*3+2] = make_float4(ca, sa, an, 0.0f);
        g_maxal[i] = 0u; g_maxiou[i] = 0u;
    }
    // negative-assumed focal BCE over this block's 256 anchors x 15 classes
    __shared__ float sc[256*Cc];
    size_t base = (size_t)blockIdx.x * (256*Cc);
    const float4* src = (const float4*)(cls + base);
    #pragma unroll
    for (int j = threadIdx.x; j < (256*Cc)/4; j += 256) ((float4*)sc)[j] = src[j];
    __syncthreads();
    float acc = 0.0f;
    int r = threadIdx.x * Cc;
    #pragma unroll
    for (int c = 0; c < Cc; c++){
        float x  = sc[r + c];
        float em = __expf(-fabsf(x));
        float t  = 1.0f + em;
        float sp = fmaxf(x, 0.0f) + __logf(t);          // softplus(x) = bce(x, t=0)
        float sg = ((x >= 0.0f) ? 1.0f : em) * __fdividef(1.0f, t);
        acc += 0.75f * sg * sg * sp;
    }
    double v = block_red((double)acc);
    if (threadIdx.x == 0) g_negpart[blockIdx.x] = v;
}

// ---- K1: warp-per-GT: candidate gather + on-demand decode + top-13 selection ----
__global__ void __launch_bounds__(128) k_topk(const float* __restrict__ cls,
                                              const float* __restrict__ raw,
                                              const float* __restrict__ reg,
                                              const int*   __restrict__ gtl,
                                              const float* __restrict__ vm){
    __shared__ float cv[4][CAND];
    __shared__ int   sci[4][CAND];
    __shared__ int   scnt[4];
    int w    = threadIdx.x >> 5;
    int lane = threadIdx.x & 31;
    int bm   = blockIdx.x*4 + w;
    if (vm[bm] == 0.0f) return;
    int b = bm >> 6;
    if (lane == 0) scnt[w] = 0;
    __syncwarp();

    float4 q0 = g_gt[3*bm], q1 = g_gt[3*bm+1], q2 = g_gt[3*bm+2];
    float gcx = q0.x, gcy = q0.y, ga = q0.z, gb = q0.w;
    float gc = q1.x, gd = q1.y, hw = q1.z, hh = q1.w;
    float ca = q2.x, sa = q2.y;
    int lbl = gtl[bm];
    float hx = hw*ca + hh*sa;   // AABB half extents (ca,sa >= 0 for ang in [0,pi/2))
    float hy = hw*sa + hh*ca;

    // phase 1: gather in-box anchor indices over AABB cell range of each level
    #pragma unroll
    for (int L = 0; L < 3; L++){
        float st  = (L == 0) ? 8.0f : (L == 1) ? 16.0f : 32.0f;
        int npl   = (L == 0) ? 128  : (L == 1) ? 64   : 32;
        int baseN = (L == 0) ? 0    : (L == 1) ? 16384 : 20480;
        float is  = __fdividef(1.0f, st);
        int ix0 = max(0,     (int)((gcx - hx)*is - 0.5f) - 1);
        int ix1 = min(npl-1, (int)((gcx + hx)*is - 0.5f) + 1);
        int iy0 = max(0,     (int)((gcy - hy)*is - 0.5f) - 1);
        int iy1 = min(npl-1, (int)((gcy + hy)*is - 0.5f) + 1);
        int nx = ix1 - ix0 + 1, ny = iy1 - iy0 + 1;
        if (nx <= 0 || ny <= 0) continue;
        int tot = nx*ny;
        for (int j = lane; j < tot; j += 32){
            int ix = ix0 + j % nx, iy = iy0 + j / nx;
            float ax = (ix + 0.5f)*st, ay = (iy + 0.5f)*st;
            float dx = ax - gcx, dy = ay - gcy;
            float xr = dx*ca + dy*sa;
            float yr = dy*ca - dx*sa;
            if (fabsf(xr) < hw && fabsf(yr) < hh){
                int p = atomicAdd(&scnt[w], 1);
                if (p < CAND) sci[w][p] = baseN + iy*npl + ix;
            }
        }
    }
    __syncwarp();
    int count = min(scnt[w], CAND);

    // phase 2: per candidate, warp-cooperative angle softmax decode + align
    // software-pipelined prefetch of next candidate's row + lane0 scalars
    int   nn = 0; float r0 = 0, r1 = 0, r2 = 0;
    float4 rg = make_float4(0,0,0,0); float clv = 0;
    if (count > 0){
        nn = sci[w][0];
        int idx = b*Nc + nn;
        const float* ra = raw + (size_t)idx*ABp;
        r0 = ra[lane]; r1 = ra[lane+32]; if (lane < 27) r2 = ra[lane+64];
        if (lane == 0){ rg = *(const float4*)(reg + (size_t)idx*4); clv = cls[(size_t)idx*Cc + lbl]; }
    }
    for (int k2 = 0; k2 < count; k2++){
        int    cn = nn; float c0 = r0, c1 = r1, c2 = r2;
        float4 crg = rg; float ccl = clv;
        if (k2 + 1 < count){
            nn = sci[w][k2+1];
            int idx = b*Nc + nn;
            const float* ra = raw + (size_t)idx*ABp;
            r0 = ra[lane]; r1 = ra[lane+32]; if (lane < 27) r2 = ra[lane+64];
            if (lane == 0){ rg = *(const float4*)(reg + (size_t)idx*4); clv = cls[(size_t)idx*Cc + lbl]; }
        }
        float e0 = __expf(c0), e1 = __expf(c1);
        float e2 = (lane < 27) ? __expf(c2) : 0.0f;
        const float SC = ANGLE_SCALE_F;
        float s  = e0 + e1 + e2;
        float wv = e0*((float)lane*SC) + e1*((float)(lane+32)*SC) + e2*((float)(lane+64)*SC);
        #pragma unroll
        for (int o = 16; o; o >>= 1){
            s  += __shfl_xor_sync(0xffffffffu, s,  o);
            wv += __shfl_xor_sync(0xffffffffu, wv, o);
        }
        if (lane == 0){
            int idx = b*Nc + cn;
            float ang = __fdividef(wv, s);
            float lse = __logf(s);
            float offx = (crg.z - crg.x)*0.5f, offy = (crg.w - crg.y)*0.5f;
            float c = __cosf(ang), sn = __sinf(ang);
            float ax, ay, st;
            if (cn < 16384)      { int ii = cn;         ax = ((ii & 127) + 0.5f)*8.0f;  ay = ((ii >> 7) + 0.5f)*8.0f;  st = 8.0f;  }
            else if (cn < 20480) { int ii = cn - 16384; ax = ((ii &  63) + 0.5f)*16.0f; ay = ((ii >> 6) + 0.5f)*16.0f; st = 16.0f; }
            else                 { int ii = cn - 20480; ax = ((ii &  31) + 0.5f)*32.0f; ay = ((ii >> 5) + 0.5f)*32.0f; st = 32.0f; }
            float X = (offx*c - offy*sn)*st + ax;
            float Y = (offx*sn + offy*c)*st + ay;
            float W = (crg.x + crg.z)*st, H = (crg.y + crg.w)*st;
            float A = W*W/12.0f, Bv = H*H/12.0f;
            float pa = A*c*c + Bv*sn*sn;
            float pb = A*sn*sn + Bv*c*c;
            float pc = (A - Bv)*c*sn;
            float pd = fmaxf(pa*pb - pc*pc, 0.0f);
            g_dec[2*idx]   = make_float4(X, Y, pa, pb);
            g_dec[2*idx+1] = make_float4(pc, pd, lse, 0.0f);
            float hd = probiou_hd(gcx, gcy, ga, gb, gc, gd, X, Y, pa, pb, pc, pd);
            float iou = fmaxf(1.0f - hd, 0.0f);
            float i2 = iou*iou;
            cv[w][k2] = fast_sig(ccl) * i2*i2*i2;   // score^1 * iou^6
        }
    }
    __syncwarp();

    // phase 3: 13 rounds max-extraction (value desc, index asc tiebreak == lax.top_k)
    int K = min(count, 13);
    for (int k = 0; k < K; k++){
        float bv = -1.0f; int bi = 0x7fffffff, bp = -1;
        for (int j = lane; j < count; j += 32){
            float v = cv[w][j];
            if (v > bv || (v == bv && sci[w][j] < bi)){ bv = v; bi = sci[w][j]; bp = j; }
        }
        #pragma unroll
        for (int o = 16; o; o >>= 1){
            float ov = __shfl_xor_sync(0xffffffffu, bv, o);
            int   oi = __shfl_xor_sync(0xffffffffu, bi, o);
            int   op = __shfl_xor_sync(0xffffffffu, bp, o);
            if (ov > bv || (ov == bv && oi < bi)){ bv = ov; bi = oi; bp = op; }
        }
        if (bv <= EPSA) break;                     // valid = topv > EPS
        if (lane == 0){
            int idx = b*Nc + bi;
            int old = atomicAdd(&g_fgm[idx], (1 << 20) | bm);
            if ((old >> 20) == 0){                 // first claim -> append once
                int p = atomicAdd(&g_npos, 1);
                g_plist[p] = idx;
            }
            cv[w][bp] = -2.0f;
        }
        __syncwarp();
    }
}

// ---- K2: resolve positives (conflict -> argmax IoU over all 64 GTs), per-GT maxima ----
__global__ void k_resolve(const float* __restrict__ cls, const int* __restrict__ gtl){
    int i = blockIdx.x*256 + threadIdx.x;
    if (i >= g_npos) return;
    int idx = g_plist[i];
    int b = idx / Nc;
    int fgm = g_fgm[idx];
    int cnt = fgm >> 20;
    float4 p0 = g_dec[2*idx], p1 = g_dec[2*idx+1];
    int m; float iou;
    if (cnt == 1){
        m = fgm & 63;
        float4 q0 = g_gt[3*(b*64+m)], q1 = g_gt[3*(b*64+m)+1];
        float hd = probiou_hd(q0.x, q0.y, q0.z, q0.w, q1.x, q1.y,
                              p0.x, p0.y, p0.z, p0.w, p1.x, p1.y);
        iou = fmaxf(1.0f - hd, 0.0f);
    } else {
        float bv = -1.0f; int bm_ = 0;
        for (int mm = 0; mm < 64; mm++){
            float4 q0 = g_gt[3*(b*64+mm)], q1 = g_gt[3*(b*64+mm)+1];
            float hd = probiou_hd(q0.x, q0.y, q0.z, q0.w, q1.x, q1.y,
                                  p0.x, p0.y, p0.z, p0.w, p1.x, p1.y);
            float io = fmaxf(1.0f - hd, 0.0f);
            if (io > bv){ bv = io; bm_ = mm; }     // first-max == jnp.argmax
        }
        m = bm_; iou = bv;
    }
    int label = gtl[b*64 + m];
    float sg = fast_sig(cls[(size_t)idx*Cc + label]);
    float i2 = iou*iou;
    float al = sg * i2*i2*i2;
    g_m[idx]  = m;
    g_al[idx] = al;
    atomicMax(&g_maxal [b*64 + m], __float_as_uint(al));
    atomicMax(&g_maxiou[b*64 + m], __float_as_uint(iou));
}

// ---- K3: positive losses (cls-correction + box + angle + norms) ----
__global__ void k_pos(const float* __restrict__ cls, const float* __restrict__ raw,
                      const int* __restrict__ gtl){
    int i = blockIdx.x*256 + threadIdx.x;
    double dC = 0.0, dB = 0.0, dA = 0.0, dS = 0.0, dN = 0.0;
    if (i < g_npos){
        int idx = g_plist[i];
        int b = idx / Nc;
        int m = g_m[idx];
        int gi = b*64 + m;
        int label = gtl[gi];
        float ma = __uint_as_float(g_maxal [gi]);
        float mi = __uint_as_float(g_maxiou[gi]);
        float na = g_al[idx] * mi * __fdividef(1.0f, ma + EPSA);
        // cls correction: replace the negative-assumed label term with the true one
        float x  = cls[(size_t)idx*Cc + label];
        float em = __expf(-fabsf(x));
        float t  = 1.0f + em;
        float sp = fmaxf(x, 0.0f) + __logf(t);
        float sg = ((x >= 0.0f) ? 1.0f : em) * __fdividef(1.0f, t);
        dC = (double)((sp - x*na)*na - sp*0.75f*sg*sg);
        // box loss
        float4 p0 = g_dec[2*idx], p1 = g_dec[2*idx+1];
        float4 q0 = g_gt[3*gi], q1 = g_gt[3*gi+1], q2 = g_gt[3*gi+2];
        float hd = probiou_hd(p0.x, p0.y, p0.z, p0.w, p1.x, p1.y,
                              q0.x, q0.y, q0.z, q0.w, q1.x, q1.y);
        dB = (double)(hd * na);
        // angle CE
        float tA = q2.z / ANGLE_SCALE_F;
        tA = fminf(fmaxf(tA, 0.0f), 89.99f);
        int li = (int)tA;
        int ri = min(li + 1, 90);
        float lw = (float)ri - tA;
        float rw = 1.0f - lw;
        float lse = p1.z;
        const float* ra = raw + (size_t)idx*ABp;
        dA = (double)((lse - ra[li])*lw + (lse - ra[ri])*rw);
        dS = (double)na;
        dN = 1.0;
    }
    double vals[5] = {dC, dB, dA, dS, dN};
    #pragma unroll
    for (int k = 0; k < 5; k++){
        double v = block_red(vals[k]);
        if (threadIdx.x == 0) g_ppart[blockIdx.x*5 + k] = v;
    }
}

// ---- K4: deterministic final reduce + scalar math ----
__global__ void k_final(float* __restrict__ out){
    int tid = threadIdx.x;
    double accC = 0.0;
    for (int j = tid; j < NEGBLK; j += 256) accC += g_negpart[j];
    double acc[5] = {0, 0, 0, 0, 0};
    for (int j = tid; j < POSBLK; j += 256){
        #pragma unroll
        for (int k = 0; k < 5; k++) acc[k] += g_ppart[j*5 + k];
    }
    __shared__ double fin[6];
    double v = block_red(accC);
    if (tid == 0) fin[0] = v;
    #pragma unroll
    for (int k = 0; k < 5; k++){
        v = block_red(acc[k]);
        if (tid == 0) fin[1 + k] = v;
    }
    __syncthreads();
    if (tid == 0){
        double ss   = fmax(fin[4], 1.0);            // score_sum
        double lcls = (fin[0] + fin[1]) / ss;       // neg sum + pos corrections
        double lbox = fin[2] / ss;
        double np_  = fmax(fin[5], 1.0);
        double lang = fin[3] / np_;
        out[0] = (float)(lcls + 2.5*lbox + 0.05*lang);
        out[1] = (float)lcls;
        out[2] = (float)lbox;
        out[3] = (float)lang;
    }
}

extern "C" void kernel_launch(void* const* d_in, const int* in_sizes, int n_in,
                              void* d_out, int out_size){
    const float* cls = (const float*)d_in[0];
    const float* reg = (const float*)d_in[1];
    const float* raw = (const float*)d_in[2];
    const int*   gtl = (const int*)  d_in[3];
    const float* gtb = (const float*)d_in[4];
    const float* vm  = (const float*)d_in[5];

    k_prep   <<<NEGBLK, 256>>>(cls, gtb);
    k_topk   <<<Bc*Mc/4, 128>>>(cls, raw, reg, gtl, vm);
    k_resolve<<<POSBLK, 256>>>(cls, gtl);
    k_pos    <<<POSBLK, 256>>>(cls, raw, gtl);
    k_final  <<<1, 256>>>((float*)d_out);
}

// round 4
// speedup vs baseline: 2.7010x; 2.7010x over previous
#include <cuda_runtime.h>
#include <math.h>
#include <float.h>
#include <stdint.h>

// Problem constants (fixed by setup_inputs)
#define Bc 16
#define Nc 21504           // 128^2 + 64^2 + 32^2 anchors
#define Mc 64
#define Cc 15
#define ABp 91             // angle bins + 1
#define BNc (Bc*Nc)        // 344064
#define NEGBLK (BNc/256)   // 1344
#define POSBLK 52          // 52*256 = 13312 >= max positives
#define CAND 768           // per-GT candidate cap (max in-box cells ~550)
#define DROWS 128          // rows per decode block
#define EPSA 1e-9f
#define ANGLE_SCALE_F ((float)((3.14159265358979323846/2.0)/90.0))

// ---- device scratch (static; no allocations) ----
__device__ float4   g_dec[BNc*2];        // per anchor: {x,y,a,b},{c,det,lse,0}
__device__ int      g_fgm[BNc];          // (count<<20) | sum(bm)  (bm valid iff count==1)
__device__ int      g_m[BNc];
__device__ float    g_al[BNc];
__device__ float4   g_gt[Bc*Mc*3];       // per GT: {cx,cy,a,b},{c,det,hw,hh},{ca,sa,ang,0}
__device__ unsigned g_maxal[Bc*Mc], g_maxiou[Bc*Mc];
__device__ int      g_npos;
__device__ int      g_done;
__device__ int      g_plist[16384];
__device__ double   g_negpart[NEGBLK];
__device__ double   g_ppart[POSBLK*5];

// ProbIoU Hellinger distance (eps=1e-3), fast transcendentals (err ~1e-6, budget 1e-3)
__device__ __forceinline__ float probiou_hd(float x1, float y1, float a1, float b1, float c1, float d1,
                                            float x2, float y2, float a2, float b2, float c2, float d2){
    float a = a1 + a2, b = b1 + b2, c = c1 + c2;
    float denom = a*b - c*c + 1e-3f;
    float dy = y1 - y2, dx = x1 - x2;
    float rd = __fdividef(1.0f, denom);
    float t1 = (a*dy*dy + b*dx*dx) * rd * 0.25f;
    float t2 = c * (-dx) * dy * rd * 0.5f;
    float t3 = 0.5f * __logf(denom * __fdividef(1.0f, 4.0f*sqrtf(d1*d2) + 1e-3f) + 1e-3f);
    float bd = fminf(fmaxf(t1 + t2 + t3, 1e-3f), 100.0f);
    return sqrtf(1.0f - __expf(-bd) + 1e-7f);
}

__device__ __forceinline__ float fast_sig(float x){
    return __fdividef(1.0f, 1.0f + __expf(-x));
}

// block reduction of a double over 256 threads; result valid on thread 0
__device__ __forceinline__ double block_red(double v){
    __shared__ double sred[8];
    #pragma unroll
    for (int o = 16; o; o >>= 1) v += __shfl_down_sync(0xffffffffu, v, o);
    int w = threadIdx.x >> 5, l = threadIdx.x & 31;
    if (l == 0) sred[w] = v;
    __syncthreads();
    if (w == 0){
        v = (l < 8) ? sred[l] : 0.0;
        #pragma unroll
        for (int o = 4; o; o >>= 1) v += __shfl_down_sync(0xffffffffu, v, o);
    }
    __syncthreads();
    return v;
}

// ---- K0: fused GT prep + counters + g_fgm memset + pure-negative focal BCE ----
__global__ void k_prep(const float* __restrict__ cls, const float* __restrict__ gtb){
    int i = blockIdx.x*256 + threadIdx.x;
    g_fgm[i] = 0;
    if (i == 0){ g_npos = 0; g_done = 0; }
    if (i < Bc*Mc){
        const float* g = gtb + i*5;
        float cx = g[0], cy = g[1], w = g[2], h = g[3], an = g[4];
        float ca = __cosf(an), sa = __sinf(an);
        float A = w*w/12.0f, B = h*h/12.0f;
        float ga = A*ca*ca + B*sa*sa;
        float gb = A*sa*sa + B*ca*ca;
        float gc = (A - B)*ca*sa;
        float gd = fmaxf(ga*gb - gc*gc, 0.0f);
        g_gt[i*3+0] = make_float4(cx, cy, ga, gb);
        g_gt[i*3+1] = make_float4(gc, gd, w*0.5f, h*0.5f);
        g_gt[i*3+2] = make_float4(ca, sa, an, 0.0f);
        g_maxal[i] = 0u; g_maxiou[i] = 0u;
    }
    // negative-assumed focal BCE over this block's 256 anchors x 15 classes
    __shared__ float sc[256*Cc];
    size_t base = (size_t)blockIdx.x * (256*Cc);
    const float4* src = (const float4*)(cls + base);
    #pragma unroll
    for (int j = threadIdx.x; j < (256*Cc)/4; j += 256) ((float4*)sc)[j] = src[j];
    __syncthreads();
    float acc = 0.0f;
    int r = threadIdx.x * Cc;
    #pragma unroll
    for (int c = 0; c < Cc; c++){
        float x  = sc[r + c];
        float em = __expf(-fabsf(x));
        float t  = 1.0f + em;
        float sp = fmaxf(x, 0.0f) + __logf(t);          // softplus(x) = bce(x, t=0)
        float sg = ((x >= 0.0f) ? 1.0f : em) * __fdividef(1.0f, t);
        acc += 0.75f * sg * sg * sp;
    }
    double v = block_red((double)acc);
    if (threadIdx.x == 0) g_negpart[blockIdx.x] = v;
}

// ---- K1: dense decode; block stages 128 contiguous rows, thread-per-row softmax ----
__global__ void __launch_bounds__(DROWS) k_decode(const float* __restrict__ raw,
                                                  const float* __restrict__ reg){
    __shared__ float sc[DROWS*ABp];                 // 46592 B
    int t = threadIdx.x;
    int row0 = blockIdx.x * DROWS;
    // coalesced stage: 128 rows * 91 floats = 2912 float4 (16B-aligned: 46592%16==0)
    const float4* src = (const float4*)(raw + (size_t)row0 * ABp);
    #pragma unroll
    for (int j = t; j < (DROWS*ABp)/4; j += DROWS) ((float4*)sc)[j] = src[j];
    __syncthreads();

    int row = row0 + t;
    const float* rr = sc + t*ABp;                   // stride 91 (odd) -> conflict-free
    float s = 0.0f, wk = 0.0f;
    #pragma unroll
    for (int k = 0; k < ABp; k++){
        float e = __expf(rr[k]);
        s  += e;
        wk  = fmaf((float)k, e, wk);
    }
    float ang = __fdividef(wk, s) * ANGLE_SCALE_F;
    float lse = __logf(s);
    float4 rd = *(const float4*)(reg + (size_t)row*4);
    float offx = (rd.z - rd.x)*0.5f, offy = (rd.w - rd.y)*0.5f;
    float c = __cosf(ang), sn = __sinf(ang);
    int n = row % Nc;
    float ax, ay, st;
    if (n < 16384)      { int ii = n;         ax = ((ii & 127) + 0.5f)*8.0f;  ay = ((ii >> 7) + 0.5f)*8.0f;  st = 8.0f;  }
    else if (n < 20480) { int ii = n - 16384; ax = ((ii &  63) + 0.5f)*16.0f; ay = ((ii >> 6) + 0.5f)*16.0f; st = 16.0f; }
    else                { int ii = n - 20480; ax = ((ii &  31) + 0.5f)*32.0f; ay = ((ii >> 5) + 0.5f)*32.0f; st = 32.0f; }
    float X = (offx*c - offy*sn)*st + ax;
    float Y = (offx*sn + offy*c)*st + ay;
    float W = (rd.x + rd.z)*st, H = (rd.y + rd.w)*st;
    float A = W*W/12.0f, Bv = H*H/12.0f;
    float pa = A*c*c + Bv*sn*sn;
    float pb = A*sn*sn + Bv*c*c;
    float pc = (A - Bv)*c*sn;
    float pd = fmaxf(pa*pb - pc*pc, 0.0f);
    g_dec[2*row]   = make_float4(X, Y, pa, pb);
    g_dec[2*row+1] = make_float4(pc, pd, lse, 0.0f);
}

// ---- K2: warp-per-GT: candidate gather + lane-parallel align + top-13 selection ----
__global__ void __launch_bounds__(128) k_topk(const float* __restrict__ cls,
                                              const int*   __restrict__ gtl,
                                              const float* __restrict__ vm){
    __shared__ float cv[4][CAND];
    __shared__ int   sci[4][CAND];
    __shared__ int   scnt[4];
    int w    = threadIdx.x >> 5;
    int lane = threadIdx.x & 31;
    int bm   = blockIdx.x*4 + w;
    if (vm[bm] == 0.0f) return;
    int b = bm >> 6;
    if (lane == 0) scnt[w] = 0;
    __syncwarp();

    float4 q0 = g_gt[3*bm], q1 = g_gt[3*bm+1], q2 = g_gt[3*bm+2];
    float gcx = q0.x, gcy = q0.y, ga = q0.z, gb = q0.w;
    float gc = q1.x, gd = q1.y, hw = q1.z, hh = q1.w;
    float ca = q2.x, sa = q2.y;
    int lbl = gtl[bm];
    float hx = hw*ca + hh*sa;   // AABB half extents (ca,sa >= 0 for ang in [0,pi/2))
    float hy = hw*sa + hh*ca;

    // phase 1: gather in-box anchor indices over AABB cell range of each level
    #pragma unroll
    for (int L = 0; L < 3; L++){
        float st  = (L == 0) ? 8.0f : (L == 1) ? 16.0f : 32.0f;
        int npl   = (L == 0) ? 128  : (L == 1) ? 64   : 32;
        int baseN = (L == 0) ? 0    : (L == 1) ? 16384 : 20480;
        float is  = __fdividef(1.0f, st);
        int ix0 = max(0,     (int)((gcx - hx)*is - 0.5f) - 1);
        int ix1 = min(npl-1, (int)((gcx + hx)*is - 0.5f) + 1);
        int iy0 = max(0,     (int)((gcy - hy)*is - 0.5f) - 1);
        int iy1 = min(npl-1, (int)((gcy + hy)*is - 0.5f) + 1);
        int nx = ix1 - ix0 + 1, ny = iy1 - iy0 + 1;
        if (nx <= 0 || ny <= 0) continue;
        int tot = nx*ny;
        for (int j = lane; j < tot; j += 32){
            int ix = ix0 + j % nx, iy = iy0 + j / nx;
            float ax = (ix + 0.5f)*st, ay = (iy + 0.5f)*st;
            float dx = ax - gcx, dy = ay - gcy;
            float xr = dx*ca + dy*sa;
            float yr = dy*ca - dx*sa;
            if (fabsf(xr) < hw && fabsf(yr) < hh){
                int p = atomicAdd(&scnt[w], 1);
                if (p < CAND) sci[w][p] = baseN + iy*npl + ix;
            }
        }
    }
    __syncwarp();
    int count = min(scnt[w], CAND);

    // phase 2: lane-parallel align over candidates (g_dec precomputed, L2-resident)
    for (int j = lane; j < count; j += 32){
        int idx = b*Nc + sci[w][j];
        float4 p0 = g_dec[2*idx], p1 = g_dec[2*idx+1];
        float hd = probiou_hd(gcx, gcy, ga, gb, gc, gd,
                              p0.x, p0.y, p0.z, p0.w, p1.x, p1.y);
        float iou = fmaxf(1.0f - hd, 0.0f);
        float sg = fast_sig(cls[(size_t)idx*Cc + lbl]);
        float i2 = iou*iou;
        cv[w][j] = sg * i2*i2*i2;                  // score^1 * iou^6
    }
    __syncwarp();

    // phase 3: 13 rounds max-extraction (value desc, index asc tiebreak == lax.top_k)
    int K = min(count, 13);
    for (int k = 0; k < K; k++){
        float bv = -1.0f; int bi = 0x7fffffff, bp = -1;
        for (int j = lane; j < count; j += 32){
            float v = cv[w][j];
            if (v > bv || (v == bv && sci[w][j] < bi)){ bv = v; bi = sci[w][j]; bp = j; }
        }
        #pragma unroll
        for (int o = 16; o; o >>= 1){
            float ov = __shfl_xor_sync(0xffffffffu, bv, o);
            int   oi = __shfl_xor_sync(0xffffffffu, bi, o);
            int   op = __shfl_xor_sync(0xffffffffu, bp, o);
            if (ov > bv || (ov == bv && oi < bi)){ bv = ov; bi = oi; bp = op; }
        }
        if (bv <= EPSA) break;                     // valid = topv > EPS
        if (lane == 0){
            int idx = b*Nc + bi;
            int old = atomicAdd(&g_fgm[idx], (1 << 20) | bm);
            if ((old >> 20) == 0){                 // first claim -> append once
                int p = atomicAdd(&g_npos, 1);
                g_plist[p] = idx;
            }
            cv[w][bp] = -2.0f;
        }
        __syncwarp();
    }
}

// ---- K3: resolve positives (conflict -> argmax IoU over all 64 GTs), per-GT maxima ----
__global__ void k_resolve(const float* __restrict__ cls, const int* __restrict__ gtl){
    int i = blockIdx.x*256 + threadIdx.x;
    if (i >= g_npos) return;
    int idx = g_plist[i];
    int b = idx / Nc;
    int fgm = g_fgm[idx];
    int cnt = fgm >> 20;
    float4 p0 = g_dec[2*idx], p1 = g_dec[2*idx+1];
    int m; float iou;
    if (cnt == 1){
        m = fgm & 63;
        float4 q0 = g_gt[3*(b*64+m)], q1 = g_gt[3*(b*64+m)+1];
        float hd = probiou_hd(q0.x, q0.y, q0.z, q0.w, q1.x, q1.y,
                              p0.x, p0.y, p0.z, p0.w, p1.x, p1.y);
        iou = fmaxf(1.0f - hd, 0.0f);
    } else {
        float bv = -1.0f; int bm_ = 0;
        for (int mm = 0; mm < 64; mm++){
            float4 q0 = g_gt[3*(b*64+mm)], q1 = g_gt[3*(b*64+mm)+1];
            float hd = probiou_hd(q0.x, q0.y, q0.z, q0.w, q1.x, q1.y,
                                  p0.x, p0.y, p0.z, p0.w, p1.x, p1.y);
            float io = fmaxf(1.0f - hd, 0.0f);
            if (io > bv){ bv = io; bm_ = mm; }     // first-max == jnp.argmax
        }
        m = bm_; iou = bv;
    }
    int label = gtl[b*64 + m];
    float sg = fast_sig(cls[(size_t)idx*Cc + label]);
    float i2 = iou*iou;
    float al = sg * i2*i2*i2;
    g_m[idx]  = m;
    g_al[idx] = al;
    atomicMax(&g_maxal [b*64 + m], __float_as_uint(al));
    atomicMax(&g_maxiou[b*64 + m], __float_as_uint(iou));
}

// ---- K4: positive losses + (last block) final reduce ----
__global__ void k_pos(const float* __restrict__ cls, const float* __restrict__ raw,
                      const int* __restrict__ gtl, float* __restrict__ out){
    int tid = threadIdx.x;
    int i = blockIdx.x*256 + tid;
    double dC = 0.0, dB = 0.0, dA = 0.0, dS = 0.0, dN = 0.0;
    if (i < g_npos){
        int idx = g_plist[i];
        int b = idx / Nc;
        int m = g_m[idx];
        int gi = b*64 + m;
        int label = gtl[gi];
        float ma = __uint_as_float(g_maxal [gi]);
        float mi = __uint_as_float(g_maxiou[gi]);
        float na = g_al[idx] * mi * __fdividef(1.0f, ma + EPSA);
        // cls correction: replace the negative-assumed label term with the true one
        float x  = cls[(size_t)idx*Cc + label];
        float em = __expf(-fabsf(x));
        float t  = 1.0f + em;
        float sp = fmaxf(x, 0.0f) + __logf(t);
        float sg = ((x >= 0.0f) ? 1.0f : em) * __fdividef(1.0f, t);
        dC = (double)((sp - x*na)*na - sp*0.75f*sg*sg);
        // box loss
        float4 p0 = g_dec[2*idx], p1 = g_dec[2*idx+1];
        float4 q0 = g_gt[3*gi], q1 = g_gt[3*gi+1], q2 = g_gt[3*gi+2];
        float hd = probiou_hd(p0.x, p0.y, p0.z, p0.w, p1.x, p1.y,
                              q0.x, q0.y, q0.z, q0.w, q1.x, q1.y);
        dB = (double)(hd * na);
        // angle CE
        float tA = q2.z / ANGLE_SCALE_F;
        tA = fminf(fmaxf(tA, 0.0f), 89.99f);
        int li = (int)tA;
        int ri = min(li + 1, 90);
        float lw = (float)ri - tA;
        float rw = 1.0f - lw;
        float lse = p1.z;
        const float* ra = raw + (size_t)idx*ABp;
        dA = (double)((lse - ra[li])*lw + (lse - ra[ri])*rw);
        dS = (double)na;
        dN = 1.0;
    }
    double vals[5] = {dC, dB, dA, dS, dN};
    #pragma unroll
    for (int k = 0; k < 5; k++){
        double v = block_red(vals[k]);
        if (tid == 0) g_ppart[blockIdx.x*5 + k] = v;
    }
    __threadfence();
    __shared__ int slast;
    if (tid == 0) slast = (atomicAdd(&g_done, 1) == POSBLK - 1) ? 1 : 0;
    __syncthreads();
    if (!slast) return;
    __threadfence();
    // final deterministic reduce
    double accC = 0.0;
    for (int j = tid; j < NEGBLK; j += 256) accC += g_negpart[j];
    double acc[5] = {0, 0, 0, 0, 0};
    for (int j = tid; j < POSBLK; j += 256){
        #pragma unroll
        for (int k = 0; k < 5; k++) acc[k] += g_ppart[j*5 + k];
    }
    __shared__ double fin[6];
    double v = block_red(accC);
    if (tid == 0) fin[0] = v;
    #pragma unroll
    for (int k = 0; k < 5; k++){
        v = block_red(acc[k]);
        if (tid == 0) fin[1 + k] = v;
    }
    __syncthreads();
    if (tid == 0){
        double ss   = fmax(fin[4], 1.0);            // score_sum
        double lcls = (fin[0] + fin[1]) / ss;       // neg sum + pos corrections
        double lbox = fin[2] / ss;
        double np_  = fmax(fin[5], 1.0);
        double lang = fin[3] / np_;
        out[0] = (float)(lcls + 2.5*lbox + 0.05*lang);
        out[1] = (float)lcls;
        out[2] = (float)lbox;
        out[3] = (float)lang;
    }
}

extern "C" void kernel_launch(void* const* d_in, const int* in_sizes, int n_in,
                              void* d_out, int out_size){
    const float* cls = (const float*)d_in[0];
    const float* reg = (const float*)d_in[1];
    const float* raw = (const float*)d_in[2];
    const int*   gtl = (const int*)  d_in[3];
    const float* gtb = (const float*)d_in[4];
    const float* vm  = (const float*)d_in[5];

    k_prep   <<<NEGBLK, 256>>>(cls, gtb);
    k_decode <<<BNc/DROWS, DROWS>>>(raw, reg);
    k_topk   <<<Bc*Mc/4, 128>>>(cls, gtl, vm);
    k_resolve<<<POSBLK, 256>>>(cls, gtl);
    k_pos    <<<POSBLK, 256>>>(cls, raw, gtl, (float*)d_out);
}